// round 8
// baseline (speedup 1.0000x reference)
#include <cuda_runtime.h>
#include <cstdint>

#define BB 64
#define TT 1024
#define II 64
#define HH 512
#define GG 1536
#define MM (BB*TT)

typedef unsigned long long u64;

__device__ float g_xg[(size_t)MM * GG];
__device__ float g_y [(size_t)MM * HH];
__device__ float g_h [2][BB * HH];
__device__ unsigned g_bar4[4];

__device__ __forceinline__ void ffma2(u64 &d, u64 a, u64 b) {
    asm("fma.rn.f32x2 %0,%1,%2,%0;" : "+l"(d) : "l"(a), "l"(b));
}
__device__ __forceinline__ u64 pack2(float x, float y) {
    u64 r; asm("mov.b64 %0,{%1,%2};" : "=l"(r) : "f"(x), "f"(y)); return r;
}
__device__ __forceinline__ float2 unpack2(u64 v) {
    float2 f; asm("mov.b64 {%0,%1},%2;" : "=f"(f.x), "=f"(f.y) : "l"(v)); return f;
}
__device__ __forceinline__ u64 add2(u64 a, u64 b) {
    asm("add.rn.f32x2 %0,%0,%1;" : "+l"(a) : "l"(b)); return a;
}

__global__ void k_zero() {
    int i = blockIdx.x * blockDim.x + threadIdx.x;
    if (i < 4) g_bar4[i] = 0u;
    float* p = &g_h[0][0];
    for (int idx = i; idx < 2 * BB * HH; idx += gridDim.x * blockDim.x) p[idx] = 0.f;
}

// C[M,N] = A[M,K] @ W[N,K]^T + bias. FFMA2 inner, double-buffered smem,
// permuted smem layouts so per-thread operand reads are contiguous LDS.128.
template <int BM, int BN, int BK, int TM, int TNP>
__global__ __launch_bounds__(256, 2)
void sgemm_bias(const float* __restrict__ A, const float* __restrict__ W,
                const float* __restrict__ bias, float* __restrict__ C,
                int M, int N, int K)
{
    __shared__ u64   As2[2][BK][BM];   // row m stored at m' = TM*(m&15) + (m>>4)
    __shared__ float Ws [2][BK][BN];   // col pair p at n' = TNP*(p&15) + (p>>4)
    constexpr int NA = BM * BK / 4 / 256;
    constexpr int NW = BN * BK / 4 / 256;
    const int tid = threadIdx.x, c = tid & 15, r = tid >> 4;
    const int m0 = blockIdx.y * BM, n0 = blockIdx.x * BN;

    u64 acc[TM][TNP];
#pragma unroll
    for (int i = 0; i < TM; i++)
#pragma unroll
        for (int j = 0; j < TNP; j++) acc[i][j] = 0ull;

#pragma unroll
    for (int q = 0; q < NA; q++) {
        int i = tid + q * 256;
        int am = i / (BK / 4), ak = (i % (BK / 4)) * 4;
        int mp = TM * (am & 15) + (am >> 4);
        float4 v = *(const float4*)(A + (size_t)(m0 + am) * K + ak);
        As2[0][ak][mp] = pack2(v.x, v.x); As2[0][ak + 1][mp] = pack2(v.y, v.y);
        As2[0][ak + 2][mp] = pack2(v.z, v.z); As2[0][ak + 3][mp] = pack2(v.w, v.w);
    }
#pragma unroll
    for (int q = 0; q < NW; q++) {
        int i = tid + q * 256;
        int wn = i / (BK / 4), wk = (i % (BK / 4)) * 4;
        int p = wn >> 1;
        int cf = 2 * (TNP * (p & 15) + (p >> 4)) + (wn & 1);
        float4 v = *(const float4*)(W + (size_t)(n0 + wn) * K + wk);
        Ws[0][wk][cf] = v.x; Ws[0][wk + 1][cf] = v.y;
        Ws[0][wk + 2][cf] = v.z; Ws[0][wk + 3][cf] = v.w;
    }
    __syncthreads();

    int buf = 0;
    for (int k0 = 0; k0 < K; k0 += BK) {
        const int kn = k0 + BK;
        float4 pa[NA], pw[NW];
        if (kn < K) {
#pragma unroll
            for (int q = 0; q < NA; q++) {
                int i = tid + q * 256;
                int am = i / (BK / 4), ak = (i % (BK / 4)) * 4;
                pa[q] = *(const float4*)(A + (size_t)(m0 + am) * K + kn + ak);
            }
#pragma unroll
            for (int q = 0; q < NW; q++) {
                int i = tid + q * 256;
                int wn = i / (BK / 4), wk = (i % (BK / 4)) * 4;
                pw[q] = *(const float4*)(W + (size_t)(n0 + wn) * K + kn + wk);
            }
        }
#pragma unroll
        for (int kk = 0; kk < BK; kk++) {
            u64 a2[TM], b2[TNP];
            const ulonglong2* ap = (const ulonglong2*)&As2[buf][kk][TM * r];
#pragma unroll
            for (int q = 0; q < TM / 2; q++) { ulonglong2 t = ap[q]; a2[2 * q] = t.x; a2[2 * q + 1] = t.y; }
            const ulonglong2* bp = (const ulonglong2*)&Ws[buf][kk][2 * TNP * c];
#pragma unroll
            for (int q = 0; q < TNP / 2; q++) { ulonglong2 t = bp[q]; b2[2 * q] = t.x; b2[2 * q + 1] = t.y; }
#pragma unroll
            for (int i = 0; i < TM; i++)
#pragma unroll
                for (int j = 0; j < TNP; j++) ffma2(acc[i][j], a2[i], b2[j]);
        }
        if (kn < K) {
            int nb = buf ^ 1;
#pragma unroll
            for (int q = 0; q < NA; q++) {
                int i = tid + q * 256;
                int am = i / (BK / 4), ak = (i % (BK / 4)) * 4;
                int mp = TM * (am & 15) + (am >> 4);
                As2[nb][ak][mp] = pack2(pa[q].x, pa[q].x);
                As2[nb][ak + 1][mp] = pack2(pa[q].y, pa[q].y);
                As2[nb][ak + 2][mp] = pack2(pa[q].z, pa[q].z);
                As2[nb][ak + 3][mp] = pack2(pa[q].w, pa[q].w);
            }
#pragma unroll
            for (int q = 0; q < NW; q++) {
                int i = tid + q * 256;
                int wn = i / (BK / 4), wk = (i % (BK / 4)) * 4;
                int p = wn >> 1;
                int cf = 2 * (TNP * (p & 15) + (p >> 4)) + (wn & 1);
                Ws[nb][wk][cf] = pw[q].x; Ws[nb][wk + 1][cf] = pw[q].y;
                Ws[nb][wk + 2][cf] = pw[q].z; Ws[nb][wk + 3][cf] = pw[q].w;
            }
        }
        __syncthreads();
        buf ^= 1;
    }
#pragma unroll
    for (int i = 0; i < TM; i++) {
        int m = m0 + r + 16 * i;
#pragma unroll
        for (int j = 0; j < TNP; j++) {
            int col = n0 + 2 * c + 32 * j;
            u64 res = add2(acc[i][j], *(const u64*)(bias + col));
            *(u64*)(C + (size_t)m * N + col) = res;
        }
    }
}

// Persistent GRU scan (R4-proven): 128 CTAs (4 bg x 32 hs) x 256 thr.
__global__ __launch_bounds__(256, 1)
void gru_scan(const float* __restrict__ w_hh, const float* __restrict__ b_hh)
{
    __shared__ float hsm[16 * 514];
    const int tid  = threadIdx.x;
    const int hsid = blockIdx.x & 31, bg = blockIdx.x >> 5;
    const int ks   = tid & 15;
    const int jl   = ((tid >> 5) << 1) | ((tid >> 4) & 1);
    const int jhid = hsid * 16 + jl;
    const int bmine = bg * 16 + ks;

    u64 w2r[48];
#pragma unroll
    for (int g = 0; g < 3; g++)
#pragma unroll
        for (int i = 0; i < 16; i++)
            w2r[g * 16 + i] = *(const u64*)(w_hh + (size_t)(g * HH + jhid) * HH + ks * 32 + 2 * i);
    const float bhr = b_hh[jhid], bhz = b_hh[HH + jhid], bhn = b_hh[2 * HH + jhid];

    const int holdIdx = (jhid >> 5) * 514 + ks * 32 + (jhid & 31);
    float2* hs2 = (float2*)hsm;
    const int dstbase = (tid >> 4) * 257 + (tid & 15);
    const float* xgp = g_xg + (size_t)bmine * TT * GG + jhid;
    float* yp = g_y + (size_t)bmine * TT * HH + jhid;
    const int hw = bmine * HH + jhid;

    float xr = __ldcg(xgp), xz = __ldcg(xgp + HH), xn = __ldcg(xgp + 2 * HH);

    for (int t = 0; t < TT; t++) {
        const float2* src = (const float2*)(g_h[t & 1] + bg * 16 * HH);
#pragma unroll
        for (int i = 0; i < 16; i++)
            hs2[dstbase + i * 16] = __ldcg(src + i * 256 + tid);
        __syncthreads();

        const u64* hseg = (const u64*)hsm + ks * 257;
        float hold = hsm[holdIdx];
        float s0[16], s1[16], s2[16];
#pragma unroll
        for (int b = 0; b < 16; b++) {
            const u64* hb = hseg + b * 16;
            u64 a0 = 0ull, a1 = 0ull, a2v = 0ull;
#pragma unroll
            for (int i = 0; i < 16; i++) {
                u64 h = hb[i];
                ffma2(a0,  h, w2r[i]);
                ffma2(a1,  h, w2r[16 + i]);
                ffma2(a2v, h, w2r[32 + i]);
            }
            float2 f0 = unpack2(a0), f1 = unpack2(a1), f2 = unpack2(a2v);
            s0[b] = f0.x + f0.y; s1[b] = f1.x + f1.y; s2[b] = f2.x + f2.y;
        }
#pragma unroll
        for (int s = 8; s >= 1; s >>= 1) {
            const bool up = (ks & s) != 0;
#pragma unroll
            for (int i = 0; i < s; i++) {
                float v0 = up ? s0[i] : s0[i + s];
                float v1 = up ? s1[i] : s1[i + s];
                float v2 = up ? s2[i] : s2[i + s];
                v0 = __shfl_xor_sync(0xffffffffu, v0, s);
                v1 = __shfl_xor_sync(0xffffffffu, v1, s);
                v2 = __shfl_xor_sync(0xffffffffu, v2, s);
                s0[i] = (up ? s0[i + s] : s0[i]) + v0;
                s1[i] = (up ? s1[i + s] : s1[i]) + v1;
                s2[i] = (up ? s2[i + s] : s2[i]) + v2;
            }
        }
        float r = 1.f / (1.f + __expf(-(xr + s0[0] + bhr)));
        float z = 1.f / (1.f + __expf(-(xz + s1[0] + bhz)));
        float n = tanhf(xn + r * (s2[0] + bhn));
        float hnew = (1.f - z) * n + z * hold;
        __stcg(&g_h[(t + 1) & 1][hw], hnew);
        yp[0] = hnew;
        xgp += GG; yp += HH;

        const float* nx = (t + 1 < TT) ? xgp : g_xg;
        xr = __ldcg(nx); xz = __ldcg(nx + HH); xn = __ldcg(nx + 2 * HH);

        __syncthreads();
        if (tid == 0) {
            __threadfence();
            unsigned tgt = (unsigned)(t + 1) * 32u;
            atomicAdd(&g_bar4[bg], 1u);
            while (*(volatile unsigned*)&g_bar4[bg] < tgt) __nanosleep(20);
        }
        __syncthreads();
    }
}

extern "C" void kernel_launch(void* const* d_in, const int* in_sizes, int n_in,
                              void* d_out, int out_size)
{
    const float* x    = (const float*)d_in[0];
    const float* wih0 = (const float*)d_in[1];
    const float* whh0 = (const float*)d_in[2];
    const float* bih0 = (const float*)d_in[3];
    const float* bhh0 = (const float*)d_in[4];
    const float* wih1 = (const float*)d_in[5];
    const float* whh1 = (const float*)d_in[6];
    const float* bih1 = (const float*)d_in[7];
    const float* bhh1 = (const float*)d_in[8];
    const float* fcw  = (const float*)d_in[9];
    const float* fcb  = (const float*)d_in[10];
    float* out = (float*)d_out;
    (void)in_sizes; (void)n_in; (void)out_size;

    float *xg, *y;
    cudaGetSymbolAddress((void**)&xg, g_xg);
    cudaGetSymbolAddress((void**)&y,  g_y);

    dim3 gxg(GG / 128, MM / 128);

    sgemm_bias<128,128,16,8,4><<<gxg, 256>>>(x, wih0, bih0, xg, MM, GG, II);
    k_zero<<<64, 256>>>();
    gru_scan<<<128, 256>>>(whh0, bhh0);

    sgemm_bias<128,128,16,8,4><<<gxg, 256>>>(y, wih1, bih1, xg, MM, GG, HH);
    k_zero<<<64, 256>>>();
    gru_scan<<<128, 256>>>(whh1, bhh1);

    sgemm_bias<128,64,16,8,2><<<dim3(1, MM / 128), 256>>>(y, fcw, fcb, out, MM, II, HH);
}

// round 10
// speedup vs baseline: 1.1895x; 1.1895x over previous
#include <cuda_runtime.h>
#include <cuda_bf16.h>
#include <cstdint>

#define BB 64
#define TT 1024
#define II 64
#define HH 512
#define GG 1536
#define MM (BB*TT)
#define SA 40   // smem row stride in bf16 elems (80B)

typedef unsigned long long u64;
typedef unsigned u32;

__device__ float g_xg[(size_t)MM * GG];
__device__ float g_y [(size_t)MM * HH];
__device__ float g_h [2][BB * HH];
__device__ unsigned g_bar4[4];

__device__ __forceinline__ void ffma2(u64 &d, u64 a, u64 b) {
    asm("fma.rn.f32x2 %0,%1,%2,%0;" : "+l"(d) : "l"(a), "l"(b));
}
__device__ __forceinline__ float2 unpack2(u64 v) {
    float2 f; asm("mov.b64 {%0,%1},%2;" : "=f"(f.x), "=f"(f.y) : "l"(v)); return f;
}
__device__ __forceinline__ u32 smem_u32(const void* p) {
    u32 a; asm("{ .reg .u64 t; cvta.to.shared.u64 t, %1; cvt.u32.u64 %0, t; }" : "=r"(a) : "l"(p));
    return a;
}
__device__ __forceinline__ void ldsm4(u32 a, u32 &r0, u32 &r1, u32 &r2, u32 &r3) {
    asm volatile("ldmatrix.sync.aligned.m8n8.x4.shared.b16 {%0,%1,%2,%3},[%4];"
                 : "=r"(r0), "=r"(r1), "=r"(r2), "=r"(r3) : "r"(a));
}
__device__ __forceinline__ void mma_bf(float* d, const u32* a, const u32* b) {
    asm volatile("mma.sync.aligned.m16n8k16.row.col.f32.bf16.bf16.f32 "
                 "{%0,%1,%2,%3},{%4,%5,%6,%7},{%8,%9},{%0,%1,%2,%3};"
                 : "+f"(d[0]), "+f"(d[1]), "+f"(d[2]), "+f"(d[3])
                 : "r"(a[0]), "r"(a[1]), "r"(a[2]), "r"(a[3]), "r"(b[0]), "r"(b[1]));
}
__device__ __forceinline__ void split2(float a, float b, u32 &h, u32 &l) {
    __nv_bfloat16 ha = __float2bfloat16(a), hb = __float2bfloat16(b);
    float ra = a - __bfloat162float(ha), rb = b - __bfloat162float(hb);
    __nv_bfloat16 la = __float2bfloat16(ra), lb = __float2bfloat16(rb);
    unsigned short uha = *(unsigned short*)&ha, uhb = *(unsigned short*)&hb;
    unsigned short ula = *(unsigned short*)&la, ulb = *(unsigned short*)&lb;
    h = (u32)uha | ((u32)uhb << 16);
    l = (u32)ula | ((u32)ulb << 16);
}
__device__ __forceinline__ void split4(float4 v, u64 &hi, u64 &lo) {
    u32 h01, l01, h23, l23;
    split2(v.x, v.y, h01, l01);
    split2(v.z, v.w, h23, l23);
    hi = (u64)h01 | ((u64)h23 << 32);
    lo = (u64)l01 | ((u64)l23 << 32);
}

__global__ void k_zero() {
    int i = blockIdx.x * blockDim.x + threadIdx.x;
    if (i < 4) g_bar4[i] = 0u;
    float* p = &g_h[0][0];
    for (int idx = i; idx < 2 * BB * HH; idx += gridDim.x * blockDim.x) p[idx] = 0.f;
}

// C[M,Nld] = A[M,K] @ W[N,K]^T + bias via split-bf16 mma.sync (HMMA).
// CTA tile 128x64, 8 warps (4 m x 2 n), warp tile 32x32, k-chunk 32.
__global__ __launch_bounds__(256, 2)
void hmma_gemm(const float* __restrict__ A, const float* __restrict__ W,
               const float* __restrict__ bias, float* __restrict__ C,
               int K, int Nld)
{
    __shared__ __align__(16) char sAhi[128 * SA * 2];
    __shared__ __align__(16) char sAlo[128 * SA * 2];
    __shared__ __align__(16) char sWhi[64 * SA * 2];
    __shared__ __align__(16) char sWlo[64 * SA * 2];

    const int tid = threadIdx.x, lane = tid & 31, wid = tid >> 5;
    const int wr = wid & 3, wn = wid >> 2;
    const int m0 = blockIdx.y * 128, n0 = blockIdx.x * 64;

    const u32 aAhi = smem_u32(sAhi), aAlo = smem_u32(sAlo);
    const u32 aWhi = smem_u32(sWhi), aWlo = smem_u32(sWlo);

    float acc[2][4][4];
#pragma unroll
    for (int i = 0; i < 2; i++)
#pragma unroll
        for (int j = 0; j < 4; j++)
#pragma unroll
            for (int q = 0; q < 4; q++) acc[i][j][q] = 0.f;

    // per-lane ldmatrix address components
    const u32 aRow = lane & 15, aKh = ((lane >> 4) & 1) * 8;
    const u32 bRow = (lane & 7) + ((lane >> 4) & 1) * 8, bKh = ((lane >> 3) & 1) * 8;

    const int nchunks = K / 32;
    for (int kc = 0; kc < nchunks; kc++) {
        // stage A: 128 rows x 32 cols fp32 -> bf16 hi/lo
#pragma unroll
        for (int q = 0; q < 4; q++) {
            int i = tid + q * 256;
            int row = i >> 3, c4 = i & 7;
            float4 v = *(const float4*)(A + (size_t)(m0 + row) * K + kc * 32 + c4 * 4);
            u64 hi, lo; split4(v, hi, lo);
            u32 off = (row * SA + c4 * 4) * 2;
            *(u64*)(sAhi + off) = hi;
            *(u64*)(sAlo + off) = lo;
        }
        // stage W: 64 rows x 32 cols
#pragma unroll
        for (int q = 0; q < 2; q++) {
            int i = tid + q * 256;
            int row = i >> 3, c4 = i & 7;
            float4 v = *(const float4*)(W + (size_t)(n0 + row) * K + kc * 32 + c4 * 4);
            u64 hi, lo; split4(v, hi, lo);
            u32 off = (row * SA + c4 * 4) * 2;
            *(u64*)(sWhi + off) = hi;
            *(u64*)(sWlo + off) = lo;
        }
        __syncthreads();

#pragma unroll
        for (int kh = 0; kh < 2; kh++) {
            u32 ahi[2][4], alo[2][4];
#pragma unroll
            for (int mf = 0; mf < 2; mf++) {
                u32 off = ((wr * 32 + mf * 16 + aRow) * SA + kh * 16 + aKh) * 2;
                ldsm4(aAhi + off, ahi[mf][0], ahi[mf][1], ahi[mf][2], ahi[mf][3]);
                ldsm4(aAlo + off, alo[mf][0], alo[mf][1], alo[mf][2], alo[mf][3]);
            }
            u32 bhi[4][2], blo[4][2];
#pragma unroll
            for (int np = 0; np < 2; np++) {
                u32 off = ((wn * 32 + np * 16 + bRow) * SA + kh * 16 + bKh) * 2;
                u32 r0, r1, r2, r3;
                ldsm4(aWhi + off, r0, r1, r2, r3);
                bhi[np * 2][0] = r0; bhi[np * 2][1] = r1;
                bhi[np * 2 + 1][0] = r2; bhi[np * 2 + 1][1] = r3;
                ldsm4(aWlo + off, r0, r1, r2, r3);
                blo[np * 2][0] = r0; blo[np * 2][1] = r1;
                blo[np * 2 + 1][0] = r2; blo[np * 2 + 1][1] = r3;
            }
#pragma unroll
            for (int mf = 0; mf < 2; mf++)
#pragma unroll
                for (int nf = 0; nf < 4; nf++) {
                    mma_bf(acc[mf][nf], ahi[mf], bhi[nf]);
                    mma_bf(acc[mf][nf], ahi[mf], blo[nf]);
                    mma_bf(acc[mf][nf], alo[mf], bhi[nf]);
                }
        }
        __syncthreads();
    }

    // epilogue: D frag rows lane/4 (+8), cols 2*(lane%4)+{0,1}
#pragma unroll
    for (int mf = 0; mf < 2; mf++) {
        int mrow = m0 + wr * 32 + mf * 16 + (lane >> 2);
#pragma unroll
        for (int nf = 0; nf < 4; nf++) {
            int col = n0 + wn * 32 + nf * 8 + 2 * (lane & 3);
            float b0 = __ldg(bias + col), b1 = __ldg(bias + col + 1);
            float2 v0 = make_float2(acc[mf][nf][0] + b0, acc[mf][nf][1] + b1);
            float2 v1 = make_float2(acc[mf][nf][2] + b0, acc[mf][nf][3] + b1);
            *(float2*)(C + (size_t)mrow * Nld + col) = v0;
            *(float2*)(C + (size_t)(mrow + 8) * Nld + col) = v1;
        }
    }
}

// ---------------- Persistent GRU scan (R4-proven) ----------------
__global__ __launch_bounds__(256, 1)
void gru_scan(const float* __restrict__ w_hh, const float* __restrict__ b_hh)
{
    __shared__ float hsm[16 * 514];
    const int tid  = threadIdx.x;
    const int hsid = blockIdx.x & 31, bg = blockIdx.x >> 5;
    const int ks   = tid & 15;
    const int jl   = ((tid >> 5) << 1) | ((tid >> 4) & 1);
    const int jhid = hsid * 16 + jl;
    const int bmine = bg * 16 + ks;

    u64 w2r[48];
#pragma unroll
    for (int g = 0; g < 3; g++)
#pragma unroll
        for (int i = 0; i < 16; i++)
            w2r[g * 16 + i] = *(const u64*)(w_hh + (size_t)(g * HH + jhid) * HH + ks * 32 + 2 * i);
    const float bhr = b_hh[jhid], bhz = b_hh[HH + jhid], bhn = b_hh[2 * HH + jhid];

    const int holdIdx = (jhid >> 5) * 514 + ks * 32 + (jhid & 31);
    float2* hs2 = (float2*)hsm;
    const int dstbase = (tid >> 4) * 257 + (tid & 15);
    const float* xgp = g_xg + (size_t)bmine * TT * GG + jhid;
    float* yp = g_y + (size_t)bmine * TT * HH + jhid;
    const int hw = bmine * HH + jhid;

    float xr = __ldcg(xgp), xz = __ldcg(xgp + HH), xn = __ldcg(xgp + 2 * HH);

    for (int t = 0; t < TT; t++) {
        const float2* src = (const float2*)(g_h[t & 1] + bg * 16 * HH);
#pragma unroll
        for (int i = 0; i < 16; i++)
            hs2[dstbase + i * 16] = __ldcg(src + i * 256 + tid);
        __syncthreads();

        const u64* hseg = (const u64*)hsm + ks * 257;
        float hold = hsm[holdIdx];
        float s0[16], s1[16], s2[16];
#pragma unroll
        for (int b = 0; b < 16; b++) {
            const u64* hb = hseg + b * 16;
            u64 a0 = 0ull, a1 = 0ull, a2v = 0ull;
#pragma unroll
            for (int i = 0; i < 16; i++) {
                u64 h = hb[i];
                ffma2(a0,  h, w2r[i]);
                ffma2(a1,  h, w2r[16 + i]);
                ffma2(a2v, h, w2r[32 + i]);
            }
            float2 f0 = unpack2(a0), f1 = unpack2(a1), f2 = unpack2(a2v);
            s0[b] = f0.x + f0.y; s1[b] = f1.x + f1.y; s2[b] = f2.x + f2.y;
        }
#pragma unroll
        for (int s = 8; s >= 1; s >>= 1) {
            const bool up = (ks & s) != 0;
#pragma unroll
            for (int i = 0; i < s; i++) {
                float v0 = up ? s0[i] : s0[i + s];
                float v1 = up ? s1[i] : s1[i + s];
                float v2 = up ? s2[i] : s2[i + s];
                v0 = __shfl_xor_sync(0xffffffffu, v0, s);
                v1 = __shfl_xor_sync(0xffffffffu, v1, s);
                v2 = __shfl_xor_sync(0xffffffffu, v2, s);
                s0[i] = (up ? s0[i + s] : s0[i]) + v0;
                s1[i] = (up ? s1[i + s] : s1[i]) + v1;
                s2[i] = (up ? s2[i + s] : s2[i]) + v2;
            }
        }
        float r = 1.f / (1.f + __expf(-(xr + s0[0] + bhr)));
        float z = 1.f / (1.f + __expf(-(xz + s1[0] + bhz)));
        float n = tanhf(xn + r * (s2[0] + bhn));
        float hnew = (1.f - z) * n + z * hold;
        __stcg(&g_h[(t + 1) & 1][hw], hnew);
        yp[0] = hnew;
        xgp += GG; yp += HH;

        const float* nx = (t + 1 < TT) ? xgp : g_xg;
        xr = __ldcg(nx); xz = __ldcg(nx + HH); xn = __ldcg(nx + 2 * HH);

        __syncthreads();
        if (tid == 0) {
            __threadfence();
            unsigned tgt = (unsigned)(t + 1) * 32u;
            atomicAdd(&g_bar4[bg], 1u);
            while (*(volatile unsigned*)&g_bar4[bg] < tgt) __nanosleep(20);
        }
        __syncthreads();
    }
}

extern "C" void kernel_launch(void* const* d_in, const int* in_sizes, int n_in,
                              void* d_out, int out_size)
{
    const float* x    = (const float*)d_in[0];
    const float* wih0 = (const float*)d_in[1];
    const float* whh0 = (const float*)d_in[2];
    const float* bih0 = (const float*)d_in[3];
    const float* bhh0 = (const float*)d_in[4];
    const float* wih1 = (const float*)d_in[5];
    const float* whh1 = (const float*)d_in[6];
    const float* bih1 = (const float*)d_in[7];
    const float* bhh1 = (const float*)d_in[8];
    const float* fcw  = (const float*)d_in[9];
    const float* fcb  = (const float*)d_in[10];
    float* out = (float*)d_out;
    (void)in_sizes; (void)n_in; (void)out_size;

    float *xg, *y;
    cudaGetSymbolAddress((void**)&xg, g_xg);
    cudaGetSymbolAddress((void**)&y,  g_y);

    // layer 0: xg0 = x @ wih0^T + bih0   [65536 x 1536], K=64
    hmma_gemm<<<dim3(GG / 64, MM / 128), 256>>>(x, wih0, bih0, xg, II, GG);
    k_zero<<<64, 256>>>();
    gru_scan<<<128, 256>>>(whh0, bhh0);

    // layer 1: xg1 = y @ wih1^T + bih1   [65536 x 1536], K=512
    hmma_gemm<<<dim3(GG / 64, MM / 128), 256>>>(y, wih1, bih1, xg, HH, GG);
    k_zero<<<64, 256>>>();
    gru_scan<<<128, 256>>>(whh1, bhh1);

    // FC: out = y @ fcw^T + fcb          [65536 x 64], K=512
    hmma_gemm<<<dim3(1, MM / 128), 256>>>(y, fcw, fcb, out, HH, II);
}